// round 9
// baseline (speedup 1.0000x reference)
#include <cuda_runtime.h>
#include <cuda_bf16.h>
#include <cstdint>

// Problem constants (match reference_code)
#define NB_NODE 100000
#define FT      256
#define OUT_FT  256
#define NB_REL  4
#define BATCH   8192
#define DEG     16

typedef unsigned long long ull;

// Scratch: v_in[b][r][f] mean-pooled neighbor features. 8192*4*256 f32 = 32 MB.
__device__ float g_vin[BATCH * NB_REL * FT];

// ---------------------------------------------------------------------------
// Packed fp32 FMA: one instruction, two fp32 lanes (sm_100+/sm_103a).
// ---------------------------------------------------------------------------
#define FMA2(d, a, b) \
    asm("fma.rn.f32x2 %0, %1, %2, %0;" : "+l"(d) : "l"(a), "l"(b))

#define CP_ASYNC_CG(smem_u32, gptr) \
    asm volatile("cp.async.cg.shared.global [%0], [%1], 16;\n" \
                 :: "r"(smem_u32), "l"(gptr))
#define CP_COMMIT() asm volatile("cp.async.commit_group;\n" ::: "memory")
#define CP_WAIT0()  asm volatile("cp.async.wait_group 0;\n" ::: "memory")

// ---------------------------------------------------------------------------
// Kernel 1: gather + mean over DEG neighbors. L2-bound (~12 TB/s LTS, at the
// measured cap). 4 (b,r) pairs per 256-thread block, 64 lanes/row, float4.
// ---------------------------------------------------------------------------
__global__ void __launch_bounds__(256, 8)
gather_mean_kernel(const float* __restrict__ features,
                   const int* __restrict__ nidx)
{
    const int sub  = threadIdx.x >> 6;
    const int lane = threadIdx.x & 63;
    const int pair = blockIdx.x * 4 + sub;

    const int* idx = nidx + pair * DEG;

    float4 s = make_float4(0.f, 0.f, 0.f, 0.f);
#pragma unroll
    for (int d = 0; d < DEG; d++) {
        const int n = __ldg(&idx[d]);
        const float4 v = __ldg(((const float4*)(features + (size_t)n * FT)) + lane);
        s.x += v.x; s.y += v.y; s.z += v.z; s.w += v.w;
    }
    const float inv = 1.0f / (float)DEG;
    s.x *= inv; s.y *= inv; s.z *= inv; s.w *= inv;
    ((float4*)(g_vin + (size_t)pair * FT))[lane] = s;
}

// ---------------------------------------------------------------------------
// Kernel 2: per-relation GEMM + bias + PReLU, mean over relations, using
// packed f32x2 FMA.
//   out[b,o] = 0.25 * sum_r prelu( sum_f v_in[b,r,f]*W[r,f,o] + b[r,o] )
//
// BM=32, BN=128, KC=32, 128 threads. tx=tid&15 owns cols {tx*4..+3} and
// {64+tx*4..+3}; ty=tid>>4 owns rows ty*4..+3. Each thread: 4x8 outputs as
// 16 f32x2 accumulators -> 16 fma.rn.f32x2 per k-step.
//   A in smem: transposed + duplicated float2 (a,a) -> 2 ulonglong2 LDS
//   B in smem: plain f32 -> 2 ulonglong2 LDS of natural pairs
// B double-buffered via cp.async.cg; A prefetched in regs; 1 sync per chunk.
// ---------------------------------------------------------------------------
#define BM 32
#define BN 128
#define KC 32
#define ASU 34              // float2 stride per k-row (pad: 16B-aligned rows)
#define NCHUNKS (NB_REL * (FT / KC))   // 4 * 8 = 32

__global__ void __launch_bounds__(128, 4)
rgcn_gemm_kernel(const float* __restrict__ W,      // [NB_REL][FT][OUT_FT]
                 const float* __restrict__ bias,   // [NB_REL][OUT_FT]
                 const float* __restrict__ prelu_a,
                 float* __restrict__ out)          // [BATCH][OUT_FT]
{
    __shared__ __align__(16) float2 As2[2][KC * ASU];  // (a,a) dup, [k][m]
    __shared__ __align__(16) float  Bs[2][KC * BN];    // [k][n]

    const int tid = threadIdx.x;
    const int tx  = tid & 15;
    const int ty  = tid >> 4;
    const int bm0 = blockIdx.x * BM;
    const int bn0 = blockIdx.y * BN;

    const int arow  = tid >> 3;     // 0..15 (and +16)
    const int acol4 = tid & 7;      // float4 index within 32 floats

    const float alpha = __ldg(prelu_a);

    const uint32_t bs_base0 = (uint32_t)__cvta_generic_to_shared(&Bs[0][0]);
    const uint32_t bs_base1 = (uint32_t)__cvta_generic_to_shared(&Bs[1][0]);

    ull acc[4][4];                  // [row][col-pair], f32x2 packed
    float run[4][8];
#pragma unroll
    for (int i = 0; i < 4; i++) {
#pragma unroll
        for (int j = 0; j < 4; j++) acc[i][j] = 0ull;
#pragma unroll
        for (int j = 0; j < 8; j++) run[i][j] = 0.f;
    }

    // ---- chunk loaders -----------------------------------------------------
    // A: global -> regs (2x float4 per thread)
    float4 aPref0, aPref1;
    {
        const size_t base0 = ((size_t)(bm0 + arow)      * NB_REL + 0) * FT + acol4 * 4;
        const size_t base1 = ((size_t)(bm0 + arow + 16) * NB_REL + 0) * FT + acol4 * 4;
        aPref0 = __ldg((const float4*)(g_vin + base0));
        aPref1 = __ldg((const float4*)(g_vin + base1));
    }
    // B: cp.async chunk 0 (r=0, kc0=0)
    {
#pragma unroll
        for (int j = 0; j < 8; j++) {
            const int idx  = tid + j * 128;
            const int brow = idx >> 5;
            const int bcol = (idx & 31) * 4;
            CP_ASYNC_CG(bs_base0 + (uint32_t)((brow * BN + bcol) * 4),
                        W + (size_t)brow * OUT_FT + bn0 + bcol);
        }
        CP_COMMIT();
    }

#pragma unroll 1
    for (int c = 0; c < NCHUNKS; c++) {
        const int buf = c & 1;

        CP_WAIT0();   // B[buf] resident

        // Store A (dup + transpose) into As2[buf]
        {
            const float a0v[4] = { aPref0.x, aPref0.y, aPref0.z, aPref0.w };
            const float a1v[4] = { aPref1.x, aPref1.y, aPref1.z, aPref1.w };
#pragma unroll
            for (int j = 0; j < 4; j++) {
                const int k = acol4 * 4 + j;
                As2[buf][k * ASU + arow]      = make_float2(a0v[j], a0v[j]);
                As2[buf][k * ASU + arow + 16] = make_float2(a1v[j], a1v[j]);
            }
        }
        __syncthreads();

        // Prefetch next chunk
        if (c + 1 < NCHUNKS) {
            const int cn  = c + 1;
            const int rn  = cn >> 3;
            const int kcn = (cn & 7) * KC;
            const size_t base0 = ((size_t)(bm0 + arow)      * NB_REL + rn) * FT + kcn + acol4 * 4;
            const size_t base1 = ((size_t)(bm0 + arow + 16) * NB_REL + rn) * FT + kcn + acol4 * 4;
            aPref0 = __ldg((const float4*)(g_vin + base0));
            aPref1 = __ldg((const float4*)(g_vin + base1));

            const float* Wr = W + (size_t)rn * FT * OUT_FT;
            const uint32_t bsb = (buf ? bs_base0 : bs_base1);
#pragma unroll
            for (int j = 0; j < 8; j++) {
                const int idx  = tid + j * 128;
                const int brow = idx >> 5;
                const int bcol = (idx & 31) * 4;
                CP_ASYNC_CG(bsb + (uint32_t)((brow * BN + bcol) * 4),
                            Wr + (size_t)(kcn + brow) * OUT_FT + bn0 + bcol);
            }
            CP_COMMIT();
        }

        // Compute this chunk: 32 k-steps x 16 fma.f32x2
        {
            const float2* __restrict__ ap = &As2[buf][ty * 4];
            const float*  __restrict__ bp = &Bs[buf][tx * 4];
#pragma unroll
            for (int k = 0; k < KC; k++) {
                const ulonglong2 av0 = *(const ulonglong2*)(ap + k * ASU);      // (a0a0,a1a1)
                const ulonglong2 av1 = *(const ulonglong2*)(ap + k * ASU + 2);  // (a2a2,a3a3)
                const ulonglong2 bv0 = *(const ulonglong2*)(bp + k * BN);       // cols tx*4..+3
                const ulonglong2 bv1 = *(const ulonglong2*)(bp + k * BN + 64);  // cols 64+tx*4..+3

                FMA2(acc[0][0], av0.x, bv0.x); FMA2(acc[0][1], av0.x, bv0.y);
                FMA2(acc[0][2], av0.x, bv1.x); FMA2(acc[0][3], av0.x, bv1.y);
                FMA2(acc[1][0], av0.y, bv0.x); FMA2(acc[1][1], av0.y, bv0.y);
                FMA2(acc[1][2], av0.y, bv1.x); FMA2(acc[1][3], av0.y, bv1.y);
                FMA2(acc[2][0], av1.x, bv0.x); FMA2(acc[2][1], av1.x, bv0.y);
                FMA2(acc[2][2], av1.x, bv1.x); FMA2(acc[2][3], av1.x, bv1.y);
                FMA2(acc[3][0], av1.y, bv0.x); FMA2(acc[3][1], av1.y, bv0.y);
                FMA2(acc[3][2], av1.y, bv1.x); FMA2(acc[3][3], av1.y, bv1.y);
            }
        }

        // Relation boundary: bias + PReLU -> run, reset acc
        if ((c & 7) == 7) {
            const int r = c >> 3;
            const float4 b0 = __ldg((const float4*)(bias + r * OUT_FT + bn0 + tx * 4));
            const float4 b1 = __ldg((const float4*)(bias + r * OUT_FT + bn0 + 64 + tx * 4));
            const float bb[8] = { b0.x, b0.y, b0.z, b0.w, b1.x, b1.y, b1.z, b1.w };
#pragma unroll
            for (int i = 0; i < 4; i++) {
#pragma unroll
                for (int j2 = 0; j2 < 4; j2++) {
                    const float lo = __uint_as_float((uint32_t)acc[i][j2]);
                    const float hi = __uint_as_float((uint32_t)(acc[i][j2] >> 32));
                    const int j = j2 * 2;
                    float h0 = lo + bb[j];
                    float h1 = hi + bb[j + 1];
                    h0 = (h0 >= 0.f) ? h0 : alpha * h0;
                    h1 = (h1 >= 0.f) ? h1 : alpha * h1;
                    run[i][j]     += h0;
                    run[i][j + 1] += h1;
                    acc[i][j2] = 0ull;
                }
            }
        }
    }

    // mean over relations, store (two float4 per row)
#pragma unroll
    for (int i = 0; i < 4; i++) {
        const int row = bm0 + ty * 4 + i;
        float4 o0, o1;
        o0.x = run[i][0] * 0.25f; o0.y = run[i][1] * 0.25f;
        o0.z = run[i][2] * 0.25f; o0.w = run[i][3] * 0.25f;
        o1.x = run[i][4] * 0.25f; o1.y = run[i][5] * 0.25f;
        o1.z = run[i][6] * 0.25f; o1.w = run[i][7] * 0.25f;
        *(float4*)(out + (size_t)row * OUT_FT + bn0 + tx * 4)      = o0;
        *(float4*)(out + (size_t)row * OUT_FT + bn0 + 64 + tx * 4) = o1;
    }
}

// ---------------------------------------------------------------------------
// Launch. Inputs (metadata order): features, neighbor_idx, W, b, prelu_a,
// node_list, k. node_list/k are unused by the reference math.
// ---------------------------------------------------------------------------
extern "C" void kernel_launch(void* const* d_in, const int* in_sizes, int n_in,
                              void* d_out, int out_size)
{
    const float* features = (const float*)d_in[0];
    const int*   nidx     = (const int*)d_in[1];
    const float* W        = (const float*)d_in[2];
    const float* bias     = (const float*)d_in[3];
    const float* prelu_a  = (const float*)d_in[4];
    float* out = (float*)d_out;

    gather_mean_kernel<<<(BATCH * NB_REL) / 4, 256>>>(features, nidx);

    // grid (8192/32, 256/128) = (256, 2) = 512 blocks, 128 threads
    dim3 grid(BATCH / BM, OUT_FT / BN);
    rgcn_gemm_kernel<<<grid, 128>>>(W, bias, prelu_a, out);
}

// round 12
// speedup vs baseline: 1.0794x; 1.0794x over previous
#include <cuda_runtime.h>
#include <cuda_bf16.h>
#include <cstdint>
#include <cstddef>

// Problem constants (match reference_code)
#define NB_NODE 100000
#define FT      256
#define OUT_FT  256
#define NB_REL  4
#define BATCH   8192
#define DEG     16

// ---------------------------------------------------------------------------
// Scratch (device globals — no allocations allowed).
//   g_vh/g_vl : v_in split into bf16 hi/lo, layout [r][b][f]  (16 MB each)
//   g_wth/gwtl: W^T split into bf16 hi/lo, layout [r][n][k]   (512 KB each)
// ---------------------------------------------------------------------------
__device__ __nv_bfloat16 g_vh[(size_t)NB_REL * BATCH * FT];
__device__ __nv_bfloat16 g_vl[(size_t)NB_REL * BATCH * FT];
__device__ __nv_bfloat16 g_wth[(size_t)NB_REL * OUT_FT * FT];
__device__ __nv_bfloat16 g_wtl[(size_t)NB_REL * OUT_FT * FT];

// ---------------------------------------------------------------------------
// PTX helpers (all baseline sm_80+ PTX — no sm_103a-gated instructions)
// ---------------------------------------------------------------------------
__device__ __forceinline__ void cp16(uint32_t dst, const void* src) {
    asm volatile("cp.async.cg.shared.global [%0], [%1], 16;\n"
                 :: "r"(dst), "l"(src));
}
#define CP_COMMIT() asm volatile("cp.async.commit_group;\n" ::: "memory")
#define CP_WAIT(n)  asm volatile("cp.async.wait_group %0;\n" :: "n"(n) : "memory")

// bf16 HMMA, fp32 accumulate: D = A(16x16) * B(16x8) + D
__device__ __forceinline__ void mma16816(float* c, const uint32_t* a,
                                         const uint32_t* b) {
    asm volatile(
        "mma.sync.aligned.m16n8k16.row.col.f32.bf16.bf16.f32 "
        "{%0,%1,%2,%3}, {%4,%5,%6,%7}, {%8,%9}, {%0,%1,%2,%3};"
        : "+f"(c[0]), "+f"(c[1]), "+f"(c[2]), "+f"(c[3])
        : "r"(a[0]), "r"(a[1]), "r"(a[2]), "r"(a[3]), "r"(b[0]), "r"(b[1]));
}

// ---------------------------------------------------------------------------
// Kernel 1: gather + mean over DEG neighbors, emit bf16 hi/lo split.
// 4 (b,r) pairs per 256-thread block, 64 lanes/row, float4 reads.
// L2-bound (512 MB reads at the ~11 TB/s LTS cap).
// ---------------------------------------------------------------------------
__global__ void __launch_bounds__(256, 8)
gather_mean_kernel(const float* __restrict__ features,
                   const int* __restrict__ nidx)
{
    const int sub  = threadIdx.x >> 6;
    const int lane = threadIdx.x & 63;
    const int pair = blockIdx.x * 4 + sub;     // pair = b*NB_REL + r
    const int b    = pair >> 2;
    const int r    = pair & 3;

    const int* idx = nidx + (size_t)pair * DEG;

    float4 s = make_float4(0.f, 0.f, 0.f, 0.f);
#pragma unroll
    for (int d = 0; d < DEG; d++) {
        const int n = __ldg(&idx[d]);
        const float4 v = __ldg(((const float4*)(features + (size_t)n * FT)) + lane);
        s.x += v.x; s.y += v.y; s.z += v.z; s.w += v.w;
    }
    const float inv = 1.0f / (float)DEG;
    s.x *= inv; s.y *= inv; s.z *= inv; s.w *= inv;

    const float sv[4] = { s.x, s.y, s.z, s.w };
    union { __nv_bfloat16 b4[4]; uint2 u; } H, L;
#pragma unroll
    for (int j = 0; j < 4; j++) {
        const __nv_bfloat16 h = __float2bfloat16_rn(sv[j]);
        H.b4[j] = h;
        L.b4[j] = __float2bfloat16_rn(sv[j] - __bfloat162float(h));
    }
    const size_t o = ((size_t)(r * BATCH + b)) * FT + lane * 4;
    *(uint2*)(g_vh + o) = H.u;
    *(uint2*)(g_vl + o) = L.u;
}

// ---------------------------------------------------------------------------
// Kernel 2: W transpose + bf16 hi/lo split.  Wt[r][n][k] = split(W[r][k][n])
// ---------------------------------------------------------------------------
__global__ void wprep_kernel(const float* __restrict__ W)
{
    const int rn = blockIdx.x;          // r*256 + n
    const int r  = rn >> 8;
    const int n  = rn & 255;
    const int k  = threadIdx.x;         // 0..255

    const float v = __ldg(&W[((size_t)r * FT + k) * OUT_FT + n]);
    const __nv_bfloat16 h = __float2bfloat16_rn(v);
    const __nv_bfloat16 l = __float2bfloat16_rn(v - __bfloat162float(h));
    const size_t o = (size_t)rn * FT + k;
    g_wth[o] = h;
    g_wtl[o] = l;
}

// ---------------------------------------------------------------------------
// Kernel 3: mma.sync bf16 split GEMM + fused epilogue.
//   D_r = Ah*Bh + Al*Bh + Ah*Bl  (fp32 accum, 3 passes)
//   out  = 0.25 * sum_r prelu(D_r + bias_r)
//
// CTA: 256 thr = 8 warps (4 m x 2 n). Tile M=128, N=64, KC=64.
// Warp tile 32x32 = 2 m-tiles x 4 n-tiles of m16n8k16.
// Smem rows padded to 72 bf16 (144 B = +4 banks/row -> conflict-free b32
// fragment loads, 16 B-aligned for cp.async). Double-buffered stages.
// ---------------------------------------------------------------------------
#define TM 128
#define TN 64
#define KC 64
#define KST 72                              // padded k-stride (bf16 units)
#define A_ELEMS (TM * KST)                  // 9216 bf16 = 18432 B
#define B_ELEMS (TN * KST)                  // 4608 bf16 =  9216 B
#define STAGE_ELEMS (A_ELEMS + B_ELEMS)     // 27648 B per stage
#define SMEM_DYN (2 * STAGE_ELEMS * 2)      // 55296 B
#define NCH (NB_REL * 3 * (FT / KC))        // 4 rel * 3 passes * 4 kc = 48

__global__ void __launch_bounds__(256, 2)
rgcn_mma_kernel(const float* __restrict__ bias,
                const float* __restrict__ prelu_a,
                float* __restrict__ out)
{
    extern __shared__ __align__(16) __nv_bfloat16 smem[];
    __shared__ float biasS[NB_REL * TN];

    const int tid  = threadIdx.x;
    const int wid  = tid >> 5;
    const int lane = tid & 31;
    const int wm   = (wid & 3) * 32;        // warp m-offset
    const int wn   = (wid >> 2) * 32;       // warp n-offset
    const int g    = lane >> 2;             // 0..7
    const int t2   = (lane & 3) * 2;        // 0,2,4,6
    const int bm0  = blockIdx.x * TM;
    const int bn0  = blockIdx.y * TN;

    // bias for this N-slice
    for (int i = tid; i < NB_REL * TN; i += 256)
        biasS[i] = __ldg(&bias[(i >> 6) * OUT_FT + bn0 + (i & 63)]);

    const uint32_t smem_b = (uint32_t)__cvta_generic_to_shared(smem);

    // chunk c -> (relation, pass, kc)
    //   r = c/12, p = (c/4)%3, kc0 = (c&3)*KC
    //   pass A: {hi, lo, hi}   pass B: {hi, hi, lo}
    auto load_chunk = [&](int c, int stage) {
        const int r   = c / 12;
        const int p   = (c >> 2) % 3;
        const int kc0 = (c & 3) * KC;
        const __nv_bfloat16* Ap = (p == 1) ? g_vl : g_vh;
        const __nv_bfloat16* Bp = (p == 2) ? g_wtl : g_wth;
        Ap += ((size_t)(r * BATCH  + bm0)) * FT + kc0;
        Bp += ((size_t)(r * OUT_FT + bn0)) * FT + kc0;
        const uint32_t stA = smem_b + (uint32_t)(stage * STAGE_ELEMS * 2);
        const uint32_t stB = stA + A_ELEMS * 2;
        // A: 128 rows x 8 chunks of 16B -> 4 per thread
#pragma unroll
        for (int j = 0; j < 4; j++) {
            const int idx = j * 256 + tid;
            const int row = idx >> 3;
            const int g8  = idx & 7;
            cp16(stA + (uint32_t)(row * (KST * 2) + g8 * 16),
                 Ap + (size_t)row * FT + g8 * 8);
        }
        // B: 64 rows x 8 chunks -> 2 per thread
#pragma unroll
        for (int j = 0; j < 2; j++) {
            const int idx = j * 256 + tid;
            const int row = idx >> 3;
            const int g8  = idx & 7;
            cp16(stB + (uint32_t)(row * (KST * 2) + g8 * 16),
                 Bp + (size_t)row * FT + g8 * 8);
        }
        CP_COMMIT();
    };

    float acc[2][4][4];                     // [m-tile][n-tile][frag]
    float run[2][4][4];
#pragma unroll
    for (int mt = 0; mt < 2; mt++)
#pragma unroll
        for (int nt = 0; nt < 4; nt++)
#pragma unroll
            for (int q = 0; q < 4; q++) { acc[mt][nt][q] = 0.f; run[mt][nt][q] = 0.f; }

    const float alpha = __ldg(prelu_a);

    load_chunk(0, 0);
    __syncthreads();   // covers biasS too

#pragma unroll 1
    for (int c = 0; c < NCH; c++) {
        const int buf = c & 1;

        if (c + 1 < NCH) {
            load_chunk(c + 1, buf ^ 1);
            CP_WAIT(1);                     // chunk c resident
        } else {
            CP_WAIT(0);
        }
        __syncthreads();

        // compute chunk c from stage buf
        const __nv_bfloat16* As = smem + buf * STAGE_ELEMS;
        const __nv_bfloat16* Bs = As + A_ELEMS;
#pragma unroll
        for (int k16 = 0; k16 < KC / 16; k16++) {
            const int k0 = k16 * 16;
            uint32_t a[2][4], b[4][2];
#pragma unroll
            for (int mt = 0; mt < 2; mt++) {
                const int mrow = wm + mt * 16 + g;
                a[mt][0] = *(const uint32_t*)(As + mrow * KST + k0 + t2);
                a[mt][1] = *(const uint32_t*)(As + (mrow + 8) * KST + k0 + t2);
                a[mt][2] = *(const uint32_t*)(As + mrow * KST + k0 + t2 + 8);
                a[mt][3] = *(const uint32_t*)(As + (mrow + 8) * KST + k0 + t2 + 8);
            }
#pragma unroll
            for (int nt = 0; nt < 4; nt++) {
                const int nrow = wn + nt * 8 + g;
                b[nt][0] = *(const uint32_t*)(Bs + nrow * KST + k0 + t2);
                b[nt][1] = *(const uint32_t*)(Bs + nrow * KST + k0 + t2 + 8);
            }
#pragma unroll
            for (int mt = 0; mt < 2; mt++)
#pragma unroll
                for (int nt = 0; nt < 4; nt++)
                    mma16816(acc[mt][nt], a[mt], b[nt]);
        }
        __syncthreads();   // protect buf^1 before next iteration's load

        // relation boundary: bias + PReLU -> run, reset acc
        if ((c % 12) == 11) {
            const int r = c / 12;
#pragma unroll
            for (int nt = 0; nt < 4; nt++) {
                const float b0 = biasS[r * TN + wn + nt * 8 + t2];
                const float b1 = biasS[r * TN + wn + nt * 8 + t2 + 1];
#pragma unroll
                for (int mt = 0; mt < 2; mt++) {
                    float h;
                    h = acc[mt][nt][0] + b0; h = (h >= 0.f) ? h : alpha * h; run[mt][nt][0] += h;
                    h = acc[mt][nt][1] + b1; h = (h >= 0.f) ? h : alpha * h; run[mt][nt][1] += h;
                    h = acc[mt][nt][2] + b0; h = (h >= 0.f) ? h : alpha * h; run[mt][nt][2] += h;
                    h = acc[mt][nt][3] + b1; h = (h >= 0.f) ? h : alpha * h; run[mt][nt][3] += h;
                    acc[mt][nt][0] = 0.f; acc[mt][nt][1] = 0.f;
                    acc[mt][nt][2] = 0.f; acc[mt][nt][3] = 0.f;
                }
            }
        }
    }

    // mean over relations, store. c-frag rows: g / g+8; cols: t2, t2+1.
#pragma unroll
    for (int mt = 0; mt < 2; mt++) {
#pragma unroll
        for (int nt = 0; nt < 4; nt++) {
            const int row0 = bm0 + wm + mt * 16 + g;
            const int col  = bn0 + wn + nt * 8 + t2;
            float2 v0 = make_float2(run[mt][nt][0] * 0.25f, run[mt][nt][1] * 0.25f);
            float2 v1 = make_float2(run[mt][nt][2] * 0.25f, run[mt][nt][3] * 0.25f);
            *(float2*)(out + (size_t)row0 * OUT_FT + col)       = v0;
            *(float2*)(out + (size_t)(row0 + 8) * OUT_FT + col) = v1;
        }
    }
}

// ---------------------------------------------------------------------------
// Launch. Inputs (metadata order): features, neighbor_idx, W, b, prelu_a,
// node_list, k. node_list/k are unused by the reference math.
// ---------------------------------------------------------------------------
extern "C" void kernel_launch(void* const* d_in, const int* in_sizes, int n_in,
                              void* d_out, int out_size)
{
    const float* features = (const float*)d_in[0];
    const int*   nidx     = (const int*)d_in[1];
    const float* W        = (const float*)d_in[2];
    const float* bias     = (const float*)d_in[3];
    const float* prelu_a  = (const float*)d_in[4];
    float* out = (float*)d_out;

    // Idempotent attribute set (not a stream op; graph-capture safe).
    cudaFuncSetAttribute(rgcn_mma_kernel,
                         cudaFuncAttributeMaxDynamicSharedMemorySize, SMEM_DYN);

    gather_mean_kernel<<<(BATCH * NB_REL) / 4, 256>>>(features, nidx);
    wprep_kernel<<<NB_REL * OUT_FT, 256>>>(W);

    dim3 grid(BATCH / TM, OUT_FT / TN);   // (64, 4) = 256 CTAs
    rgcn_mma_kernel<<<grid, 256, SMEM_DYN>>>(bias, prelu_a, out);
}

// round 13
// speedup vs baseline: 1.6862x; 1.5622x over previous
#include <cuda_runtime.h>
#include <cuda_bf16.h>
#include <cstdint>
#include <cstddef>

// Problem constants (match reference_code)
#define NB_NODE 100000
#define FT      256
#define OUT_FT  256
#define NB_REL  4
#define BATCH   8192
#define DEG     16

// ---------------------------------------------------------------------------
// Scratch (device globals — no allocations allowed).
//   g_vh/g_vl : v_in split into bf16 hi/lo, layout [r][b][f]  (16 MB each)
//   g_wth/gwtl: W^T split into bf16 hi/lo, layout [r][n][k]   (512 KB each)
// ---------------------------------------------------------------------------
__device__ __nv_bfloat16 g_vh[(size_t)NB_REL * BATCH * FT];
__device__ __nv_bfloat16 g_vl[(size_t)NB_REL * BATCH * FT];
__device__ __nv_bfloat16 g_wth[(size_t)NB_REL * OUT_FT * FT];
__device__ __nv_bfloat16 g_wtl[(size_t)NB_REL * OUT_FT * FT];

// ---------------------------------------------------------------------------
// PTX helpers (all baseline sm_80+ PTX — no sm_103a-gated instructions)
// ---------------------------------------------------------------------------
__device__ __forceinline__ void cp16(uint32_t dst, const void* src) {
    asm volatile("cp.async.cg.shared.global [%0], [%1], 16;\n"
                 :: "r"(dst), "l"(src));
}
#define CP_COMMIT() asm volatile("cp.async.commit_group;\n" ::: "memory")
#define CP_WAIT(n)  asm volatile("cp.async.wait_group %0;\n" :: "n"(n) : "memory")

// bf16 HMMA, fp32 accumulate: D = A(16x16) * B(16x8) + D
__device__ __forceinline__ void mma16816(float* c, const uint32_t* a,
                                         const uint32_t* b) {
    asm volatile(
        "mma.sync.aligned.m16n8k16.row.col.f32.bf16.bf16.f32 "
        "{%0,%1,%2,%3}, {%4,%5,%6,%7}, {%8,%9}, {%0,%1,%2,%3};"
        : "+f"(c[0]), "+f"(c[1]), "+f"(c[2]), "+f"(c[3])
        : "r"(a[0]), "r"(a[1]), "r"(a[2]), "r"(a[3]), "r"(b[0]), "r"(b[1]));
}

// ---------------------------------------------------------------------------
// Kernel 1: fused prep.
//  blocks [0, 8192): gather + mean over DEG neighbors -> bf16 hi/lo split.
//  blocks [8192, 9216): W transpose + bf16 hi/lo split.
// Gather is DRAM-bound (random rows of the 100 MB table, ~50% L2 hit).
// ---------------------------------------------------------------------------
__global__ void __launch_bounds__(256, 8)
prep_kernel(const float* __restrict__ features,
            const int* __restrict__ nidx,
            const float* __restrict__ W)
{
    if (blockIdx.x >= 8192) {
        // ---- W prep: Wt[r][n][k] = split(W[r][k][n]) ----
        const int rn = blockIdx.x - 8192;   // r*256 + n
        const int r  = rn >> 8;
        const int n  = rn & 255;
        const int k  = threadIdx.x;
        const float v = __ldg(&W[((size_t)r * FT + k) * OUT_FT + n]);
        const __nv_bfloat16 h = __float2bfloat16_rn(v);
        const __nv_bfloat16 l = __float2bfloat16_rn(v - __bfloat162float(h));
        const size_t o = (size_t)rn * FT + k;
        g_wth[o] = h;
        g_wtl[o] = l;
        return;
    }

    const int sub  = threadIdx.x >> 6;
    const int lane = threadIdx.x & 63;
    const int pair = blockIdx.x * 4 + sub;     // pair = b*NB_REL + r
    const int b    = pair >> 2;
    const int r    = pair & 3;

    const int* idx = nidx + (size_t)pair * DEG;

    float4 s = make_float4(0.f, 0.f, 0.f, 0.f);
#pragma unroll
    for (int d = 0; d < DEG; d++) {
        const int n = __ldg(&idx[d]);
        const float4 v = __ldg(((const float4*)(features + (size_t)n * FT)) + lane);
        s.x += v.x; s.y += v.y; s.z += v.z; s.w += v.w;
    }
    const float inv = 1.0f / (float)DEG;
    s.x *= inv; s.y *= inv; s.z *= inv; s.w *= inv;

    const float sv[4] = { s.x, s.y, s.z, s.w };
    union { __nv_bfloat16 b4[4]; uint2 u; } H, L;
#pragma unroll
    for (int j = 0; j < 4; j++) {
        const __nv_bfloat16 h = __float2bfloat16_rn(sv[j]);
        H.b4[j] = h;
        L.b4[j] = __float2bfloat16_rn(sv[j] - __bfloat162float(h));
    }
    const size_t o = ((size_t)(r * BATCH + b)) * FT + lane * 4;
    *(uint2*)(g_vh + o) = H.u;
    *(uint2*)(g_vl + o) = L.u;
}

// ---------------------------------------------------------------------------
// Kernel 2: mma.sync bf16 split GEMM + fused epilogue.
//   D_r = Ah*Bh + Al*Bh + Ah*Bl  (fp32 accum, 3 passes from ONE residency)
//   out  = 0.25 * sum_r prelu(D_r + bias_r)
//
// Chunk = (relation, kc): all four tiles (Ah, Al, Bh, Bl) co-resident, so
// aH fragments feed both B operands and bH fragments feed both A operands
// (24 MMAs per 32 fragment loads per k16 -> ~170 B crossbar/HMMA).
// CTA: 256 thr = 8 warps (4 m x 2 n). Tile M=128, N=64, KC=64.
// Smem rows padded to 72 bf16 (144 B) -> conflict-free b32 fragment loads.
// Double-buffered stages, 16 chunks.
// ---------------------------------------------------------------------------
#define TM 128
#define TN 64
#define KC 64
#define KST 72                              // padded k-stride (bf16 units)
#define A_ELEMS (TM * KST)                  // 9216 bf16 = 18432 B per tile
#define B_ELEMS (TN * KST)                  // 4608 bf16 =  9216 B per tile
#define STAGE_ELEMS (2 * A_ELEMS + 2 * B_ELEMS)   // Ah,Al,Bh,Bl = 55296 B
#define SMEM_DYN (2 * STAGE_ELEMS * 2)      // 110592 B
#define NCH (NB_REL * (FT / KC))            // 16 chunks

__global__ void __launch_bounds__(256, 2)
rgcn_mma_kernel(const float* __restrict__ bias,
                const float* __restrict__ prelu_a,
                float* __restrict__ out)
{
    extern __shared__ __align__(16) __nv_bfloat16 smem[];
    __shared__ float biasS[NB_REL * TN];

    const int tid  = threadIdx.x;
    const int wid  = tid >> 5;
    const int lane = tid & 31;
    const int wm   = (wid & 3) * 32;        // warp m-offset
    const int wn   = (wid >> 2) * 32;       // warp n-offset
    const int g    = lane >> 2;             // 0..7
    const int t2   = (lane & 3) * 2;        // 0,2,4,6
    const int bm0  = blockIdx.x * TM;
    const int bn0  = blockIdx.y * TN;

    for (int i = tid; i < NB_REL * TN; i += 256)
        biasS[i] = __ldg(&bias[(i >> 6) * OUT_FT + bn0 + (i & 63)]);

    const uint32_t smem_b = (uint32_t)__cvta_generic_to_shared(smem);

    // chunk c -> relation r = c/4, kc0 = (c&3)*KC. Loads Ah,Al,Bh,Bl.
    auto load_chunk = [&](int c, int stage) {
        const int r   = c >> 2;
        const int kc0 = (c & 3) * KC;
        const size_t aoff = ((size_t)(r * BATCH  + bm0)) * FT + kc0;
        const size_t boff = ((size_t)(r * OUT_FT + bn0)) * FT + kc0;
        const uint32_t stAH = smem_b + (uint32_t)(stage * STAGE_ELEMS * 2);
        const uint32_t stAL = stAH + A_ELEMS * 2;
        const uint32_t stBH = stAL + A_ELEMS * 2;
        const uint32_t stBL = stBH + B_ELEMS * 2;
        // A tiles: 128 rows x 8 x 16B each -> 4 cp16/thread/tile
#pragma unroll
        for (int j = 0; j < 4; j++) {
            const int idx = j * 256 + tid;
            const int row = idx >> 3;
            const int g8  = idx & 7;
            const uint32_t d = (uint32_t)(row * (KST * 2) + g8 * 16);
            const size_t   s = aoff + (size_t)row * FT + g8 * 8;
            cp16(stAH + d, g_vh + s);
            cp16(stAL + d, g_vl + s);
        }
        // B tiles: 64 rows x 8 x 16B -> 2 cp16/thread/tile
#pragma unroll
        for (int j = 0; j < 2; j++) {
            const int idx = j * 256 + tid;
            const int row = idx >> 3;
            const int g8  = idx & 7;
            const uint32_t d = (uint32_t)(row * (KST * 2) + g8 * 16);
            const size_t   s = boff + (size_t)row * FT + g8 * 8;
            cp16(stBH + d, g_wth + s);
            cp16(stBL + d, g_wtl + s);
        }
        CP_COMMIT();
    };

    float acc[2][4][4];                     // [m-tile][n-tile][frag]
    float run[2][4][4];
#pragma unroll
    for (int mt = 0; mt < 2; mt++)
#pragma unroll
        for (int nt = 0; nt < 4; nt++)
#pragma unroll
            for (int q = 0; q < 4; q++) { acc[mt][nt][q] = 0.f; run[mt][nt][q] = 0.f; }

    const float alpha = __ldg(prelu_a);

    load_chunk(0, 0);
    __syncthreads();   // covers biasS too

#pragma unroll 1
    for (int c = 0; c < NCH; c++) {
        const int buf = c & 1;

        if (c + 1 < NCH) {
            load_chunk(c + 1, buf ^ 1);
            CP_WAIT(1);                     // chunk c resident
        } else {
            CP_WAIT(0);
        }
        __syncthreads();

        const __nv_bfloat16* AsH = smem + buf * STAGE_ELEMS;
        const __nv_bfloat16* AsL = AsH + A_ELEMS;
        const __nv_bfloat16* BsH = AsL + A_ELEMS;
        const __nv_bfloat16* BsL = BsH + B_ELEMS;

#pragma unroll
        for (int k16 = 0; k16 < KC / 16; k16++) {
            const int k0 = k16 * 16;
            uint32_t aH[2][4], aL[2][4], bH[4][2], bL[4][2];
#pragma unroll
            for (int mt = 0; mt < 2; mt++) {
                const int mrow = wm + mt * 16 + g;
                aH[mt][0] = *(const uint32_t*)(AsH + mrow * KST + k0 + t2);
                aH[mt][1] = *(const uint32_t*)(AsH + (mrow + 8) * KST + k0 + t2);
                aH[mt][2] = *(const uint32_t*)(AsH + mrow * KST + k0 + t2 + 8);
                aH[mt][3] = *(const uint32_t*)(AsH + (mrow + 8) * KST + k0 + t2 + 8);
                aL[mt][0] = *(const uint32_t*)(AsL + mrow * KST + k0 + t2);
                aL[mt][1] = *(const uint32_t*)(AsL + (mrow + 8) * KST + k0 + t2);
                aL[mt][2] = *(const uint32_t*)(AsL + mrow * KST + k0 + t2 + 8);
                aL[mt][3] = *(const uint32_t*)(AsL + (mrow + 8) * KST + k0 + t2 + 8);
            }
#pragma unroll
            for (int nt = 0; nt < 4; nt++) {
                const int nrow = wn + nt * 8 + g;
                bH[nt][0] = *(const uint32_t*)(BsH + nrow * KST + k0 + t2);
                bH[nt][1] = *(const uint32_t*)(BsH + nrow * KST + k0 + t2 + 8);
                bL[nt][0] = *(const uint32_t*)(BsL + nrow * KST + k0 + t2);
                bL[nt][1] = *(const uint32_t*)(BsL + nrow * KST + k0 + t2 + 8);
            }
            // 3 passes from the same fragments: AhBh, AlBh, AhBl
#pragma unroll
            for (int mt = 0; mt < 2; mt++)
#pragma unroll
                for (int nt = 0; nt < 4; nt++) {
                    mma16816(acc[mt][nt], aH[mt], bH[nt]);
                    mma16816(acc[mt][nt], aL[mt], bH[nt]);
                    mma16816(acc[mt][nt], aH[mt], bL[nt]);
                }
        }
        __syncthreads();   // protect buf^1 before next iteration's load

        // relation boundary: bias + PReLU -> run, reset acc
        if ((c & 3) == 3) {
            const int r = c >> 2;
#pragma unroll
            for (int nt = 0; nt < 4; nt++) {
                const float b0 = biasS[r * TN + wn + nt * 8 + t2];
                const float b1 = biasS[r * TN + wn + nt * 8 + t2 + 1];
#pragma unroll
                for (int mt = 0; mt < 2; mt++) {
                    float h;
                    h = acc[mt][nt][0] + b0; h = (h >= 0.f) ? h : alpha * h; run[mt][nt][0] += h;
                    h = acc[mt][nt][1] + b1; h = (h >= 0.f) ? h : alpha * h; run[mt][nt][1] += h;
                    h = acc[mt][nt][2] + b0; h = (h >= 0.f) ? h : alpha * h; run[mt][nt][2] += h;
                    h = acc[mt][nt][3] + b1; h = (h >= 0.f) ? h : alpha * h; run[mt][nt][3] += h;
                    acc[mt][nt][0] = 0.f; acc[mt][nt][1] = 0.f;
                    acc[mt][nt][2] = 0.f; acc[mt][nt][3] = 0.f;
                }
            }
        }
    }

    // mean over relations, store. c-frag rows: g / g+8; cols: t2, t2+1.
#pragma unroll
    for (int mt = 0; mt < 2; mt++) {
#pragma unroll
        for (int nt = 0; nt < 4; nt++) {
            const int row0 = bm0 + wm + mt * 16 + g;
            const int col  = bn0 + wn + nt * 8 + t2;
            float2 v0 = make_float2(run[mt][nt][0] * 0.25f, run[mt][nt][1] * 0.25f);
            float2 v1 = make_float2(run[mt][nt][2] * 0.25f, run[mt][nt][3] * 0.25f);
            *(float2*)(out + (size_t)row0 * OUT_FT + col)       = v0;
            *(float2*)(out + (size_t)(row0 + 8) * OUT_FT + col) = v1;
        }
    }
}

// ---------------------------------------------------------------------------
// Launch. Inputs (metadata order): features, neighbor_idx, W, b, prelu_a,
// node_list, k. node_list/k are unused by the reference math.
// ---------------------------------------------------------------------------
extern "C" void kernel_launch(void* const* d_in, const int* in_sizes, int n_in,
                              void* d_out, int out_size)
{
    const float* features = (const float*)d_in[0];
    const int*   nidx     = (const int*)d_in[1];
    const float* W        = (const float*)d_in[2];
    const float* bias     = (const float*)d_in[3];
    const float* prelu_a  = (const float*)d_in[4];
    float* out = (float*)d_out;

    // Idempotent attribute set (not a stream op; graph-capture safe).
    cudaFuncSetAttribute(rgcn_mma_kernel,
                         cudaFuncAttributeMaxDynamicSharedMemorySize, SMEM_DYN);

    // Fused gather (8192 blocks) + W prep (1024 blocks)
    prep_kernel<<<8192 + NB_REL * OUT_FT / 1, 256>>>(features, nidx, W);

    dim3 grid(BATCH / TM, OUT_FT / TN);   // (64, 4) = 256 CTAs
    rgcn_mma_kernel<<<grid, 256, SMEM_DYN>>>(bias, prelu_a, out);
}

// round 14
// speedup vs baseline: 1.7334x; 1.0280x over previous
#include <cuda_runtime.h>
#include <cuda_bf16.h>
#include <cstdint>
#include <cstddef>

// Problem constants (match reference_code)
#define NB_NODE 100000
#define FT      256
#define OUT_FT  256
#define NB_REL  4
#define BATCH   8192
#define DEG     16

// ---------------------------------------------------------------------------
// Scratch (device globals — no allocations allowed).
//   g_vh/g_vl : v_in split into bf16 hi/lo, layout [r][b][f]  (16 MB each)
//   g_wth/gwtl: W^T split into bf16 hi/lo, layout [r][n][k]   (512 KB each)
// ---------------------------------------------------------------------------
__device__ __nv_bfloat16 g_vh[(size_t)NB_REL * BATCH * FT];
__device__ __nv_bfloat16 g_vl[(size_t)NB_REL * BATCH * FT];
__device__ __nv_bfloat16 g_wth[(size_t)NB_REL * OUT_FT * FT];
__device__ __nv_bfloat16 g_wtl[(size_t)NB_REL * OUT_FT * FT];

// ---------------------------------------------------------------------------
// PTX helpers (all baseline sm_75/sm_80 PTX — no sm_103a-gated instructions)
// ---------------------------------------------------------------------------
__device__ __forceinline__ void cp16(uint32_t dst, const void* src) {
    asm volatile("cp.async.cg.shared.global [%0], [%1], 16;\n"
                 :: "r"(dst), "l"(src));
}
#define CP_COMMIT() asm volatile("cp.async.commit_group;\n" ::: "memory")
#define CP_WAIT(n)  asm volatile("cp.async.wait_group %0;\n" :: "n"(n) : "memory")

// bf16 HMMA, fp32 accumulate: D = A(16x16) * B(16x8) + D
__device__ __forceinline__ void mma16816(float* c, const uint32_t* a,
                                         const uint32_t* b) {
    asm volatile(
        "mma.sync.aligned.m16n8k16.row.col.f32.bf16.bf16.f32 "
        "{%0,%1,%2,%3}, {%4,%5,%6,%7}, {%8,%9}, {%0,%1,%2,%3};"
        : "+f"(c[0]), "+f"(c[1]), "+f"(c[2]), "+f"(c[3])
        : "r"(a[0]), "r"(a[1]), "r"(a[2]), "r"(a[3]), "r"(b[0]), "r"(b[1]));
}

// ldmatrix x4: four 8x8 b16 matrices, one per 8-lane address group
#define LDSM4(R, addr) \
    asm volatile("ldmatrix.sync.aligned.m8n8.x4.shared.b16 {%0,%1,%2,%3}, [%4];" \
                 : "=r"((R)[0]), "=r"((R)[1]), "=r"((R)[2]), "=r"((R)[3]) \
                 : "r"(addr))

// streaming (evict-first) stores to keep the feature table resident in L2
__device__ __forceinline__ void stcs_u2(void* p, uint2 v) {
    asm volatile("st.global.cs.v2.u32 [%0], {%1, %2};"
                 :: "l"(p), "r"(v.x), "r"(v.y) : "memory");
}

// ---------------------------------------------------------------------------
// Kernel 1: fused prep.
//  blocks [0, 8192): gather + mean over DEG neighbors -> bf16 hi/lo split.
//  blocks [8192, 9216): W transpose + bf16 hi/lo split.
// Gather is DRAM/L2 bound; .cs writes avoid polluting L2's copy of features.
// ---------------------------------------------------------------------------
__global__ void __launch_bounds__(256, 8)
prep_kernel(const float* __restrict__ features,
            const int* __restrict__ nidx,
            const float* __restrict__ W)
{
    if (blockIdx.x >= 8192) {
        // ---- W prep: Wt[r][n][k] = split(W[r][k][n]) ----
        const int rn = blockIdx.x - 8192;   // r*256 + n
        const int r  = rn >> 8;
        const int n  = rn & 255;
        const int k  = threadIdx.x;
        const float v = __ldg(&W[((size_t)r * FT + k) * OUT_FT + n]);
        const __nv_bfloat16 h = __float2bfloat16_rn(v);
        const __nv_bfloat16 l = __float2bfloat16_rn(v - __bfloat162float(h));
        const size_t o = (size_t)rn * FT + k;
        g_wth[o] = h;
        g_wtl[o] = l;
        return;
    }

    const int sub  = threadIdx.x >> 6;
    const int lane = threadIdx.x & 63;
    const int pair = blockIdx.x * 4 + sub;     // pair = b*NB_REL + r
    const int b    = pair >> 2;
    const int r    = pair & 3;

    const int* idx = nidx + (size_t)pair * DEG;

    float4 s = make_float4(0.f, 0.f, 0.f, 0.f);
#pragma unroll
    for (int d = 0; d < DEG; d++) {
        const int n = __ldg(&idx[d]);
        const float4 v = __ldg(((const float4*)(features + (size_t)n * FT)) + lane);
        s.x += v.x; s.y += v.y; s.z += v.z; s.w += v.w;
    }
    const float inv = 1.0f / (float)DEG;
    s.x *= inv; s.y *= inv; s.z *= inv; s.w *= inv;

    const float sv[4] = { s.x, s.y, s.z, s.w };
    union { __nv_bfloat16 b4[4]; uint2 u; } H, L;
#pragma unroll
    for (int j = 0; j < 4; j++) {
        const __nv_bfloat16 h = __float2bfloat16_rn(sv[j]);
        H.b4[j] = h;
        L.b4[j] = __float2bfloat16_rn(sv[j] - __bfloat162float(h));
    }
    const size_t o = ((size_t)(r * BATCH + b)) * FT + lane * 4;
    stcs_u2(g_vh + o, H.u);
    stcs_u2(g_vl + o, L.u);
}

// ---------------------------------------------------------------------------
// Kernel 2: mma.sync bf16 split GEMM + fused epilogue.
//   D_r = Ah*Bh + Al*Bh + Ah*Bl  (fp32 accum, 3 passes from ONE residency)
//   out  = 0.25 * sum_r prelu(D_r + bias_r)
//
// Chunk = (relation, kc): Ah, Al, Bh, Bl co-resident. Fragments loaded via
// ldmatrix.x4 (8 LDSM vs 32 LDS.32 per warp-k16), KST=72 keeps every 8x8
// matrix phase conflict-free (row stride 36 words -> banks 4r mod 32).
// CTA: 256 thr = 8 warps (4 m x 2 n). Tile M=128, N=64, KC=64, 2 stages.
// ---------------------------------------------------------------------------
#define TM 128
#define TN 64
#define KC 64
#define KST 72                              // padded k-stride (bf16 units)
#define A_ELEMS (TM * KST)                  // 18432 B per tile
#define B_ELEMS (TN * KST)                  //  9216 B per tile
#define STAGE_ELEMS (2 * A_ELEMS + 2 * B_ELEMS)   // Ah,Al,Bh,Bl = 55296 B
#define SMEM_DYN (2 * STAGE_ELEMS * 2)      // 110592 B
#define NCH (NB_REL * (FT / KC))            // 16 chunks

__global__ void __launch_bounds__(256, 2)
rgcn_mma_kernel(const float* __restrict__ bias,
                const float* __restrict__ prelu_a,
                float* __restrict__ out)
{
    extern __shared__ __align__(16) __nv_bfloat16 smem[];
    __shared__ float biasS[NB_REL * TN];

    const int tid  = threadIdx.x;
    const int wid  = tid >> 5;
    const int lane = tid & 31;
    const int wm   = (wid & 3) * 32;        // warp m-offset
    const int wn   = (wid >> 2) * 32;       // warp n-offset
    const int g    = lane >> 2;             // 0..7
    const int t2   = (lane & 3) * 2;        // 0,2,4,6
    const int bm0  = blockIdx.x * TM;
    const int bn0  = blockIdx.y * TN;

    for (int i = tid; i < NB_REL * TN; i += 256)
        biasS[i] = __ldg(&bias[(i >> 6) * OUT_FT + bn0 + (i & 63)]);

    const uint32_t smem_b = (uint32_t)__cvta_generic_to_shared(smem);

    // ldmatrix per-lane byte offsets within a tile (constant all kernel):
    //  A x4 (per mt): rows (lane&15), k-half (lane>>4)   [a0,a1,a2,a3]
    //  B x4 (per nt-pair p): row p*16 + (lane>>4)*8 + (lane&7),
    //                        k-half ((lane>>3)&1)        [b(2p)0,b(2p)1,b(2p+1)0,b(2p+1)1]
    uint32_t aOff[2], bOff[2];
#pragma unroll
    for (int mt = 0; mt < 2; mt++)
        aOff[mt] = (uint32_t)(((wm + mt * 16 + (lane & 15)) * KST +
                               ((lane >> 4) * 8)) * 2);
#pragma unroll
    for (int p = 0; p < 2; p++)
        bOff[p] = (uint32_t)(((wn + p * 16 + ((lane >> 4) << 3) + (lane & 7)) * KST +
                              (((lane >> 3) & 1) << 3)) * 2);

    // chunk c -> relation r = c/4, kc0 = (c&3)*KC. Loads Ah,Al,Bh,Bl.
    auto load_chunk = [&](int c, int stage) {
        const int r   = c >> 2;
        const int kc0 = (c & 3) * KC;
        const size_t aoff = ((size_t)(r * BATCH  + bm0)) * FT + kc0;
        const size_t boff = ((size_t)(r * OUT_FT + bn0)) * FT + kc0;
        const uint32_t stAH = smem_b + (uint32_t)(stage * STAGE_ELEMS * 2);
        const uint32_t stAL = stAH + A_ELEMS * 2;
        const uint32_t stBH = stAL + A_ELEMS * 2;
        const uint32_t stBL = stBH + B_ELEMS * 2;
#pragma unroll
        for (int j = 0; j < 4; j++) {
            const int idx = j * 256 + tid;
            const int row = idx >> 3;
            const int g8  = idx & 7;
            const uint32_t d = (uint32_t)(row * (KST * 2) + g8 * 16);
            const size_t   s = aoff + (size_t)row * FT + g8 * 8;
            cp16(stAH + d, g_vh + s);
            cp16(stAL + d, g_vl + s);
        }
#pragma unroll
        for (int j = 0; j < 2; j++) {
            const int idx = j * 256 + tid;
            const int row = idx >> 3;
            const int g8  = idx & 7;
            const uint32_t d = (uint32_t)(row * (KST * 2) + g8 * 16);
            const size_t   s = boff + (size_t)row * FT + g8 * 8;
            cp16(stBH + d, g_wth + s);
            cp16(stBL + d, g_wtl + s);
        }
        CP_COMMIT();
    };

    float acc[2][4][4];                     // [m-tile][n-tile][frag]
    float run[2][4][4];
#pragma unroll
    for (int mt = 0; mt < 2; mt++)
#pragma unroll
        for (int nt = 0; nt < 4; nt++)
#pragma unroll
            for (int q = 0; q < 4; q++) { acc[mt][nt][q] = 0.f; run[mt][nt][q] = 0.f; }

    const float alpha = __ldg(prelu_a);

    load_chunk(0, 0);
    __syncthreads();   // covers biasS too

#pragma unroll 1
    for (int c = 0; c < NCH; c++) {
        const int buf = c & 1;

        if (c + 1 < NCH) {
            load_chunk(c + 1, buf ^ 1);
            CP_WAIT(1);                     // chunk c resident
        } else {
            CP_WAIT(0);
        }
        __syncthreads();

        const uint32_t stAH = smem_b + (uint32_t)(buf * STAGE_ELEMS * 2);
        const uint32_t stAL = stAH + A_ELEMS * 2;
        const uint32_t stBH = stAL + A_ELEMS * 2;
        const uint32_t stBL = stBH + B_ELEMS * 2;

#pragma unroll
        for (int k16 = 0; k16 < KC / 16; k16++) {
            const uint32_t kB = (uint32_t)(k16 * 32);   // 16 bf16 = 32 bytes
            uint32_t aH[8], aL[8], bH[8], bL[8];
            LDSM4(aH,     stAH + aOff[0] + kB);
            LDSM4(aH + 4, stAH + aOff[1] + kB);
            LDSM4(aL,     stAL + aOff[0] + kB);
            LDSM4(aL + 4, stAL + aOff[1] + kB);
            LDSM4(bH,     stBH + bOff[0] + kB);
            LDSM4(bH + 4, stBH + bOff[1] + kB);
            LDSM4(bL,     stBL + bOff[0] + kB);
            LDSM4(bL + 4, stBL + bOff[1] + kB);
            // 3 passes from the same fragments: AhBh, AlBh, AhBl
#pragma unroll
            for (int mt = 0; mt < 2; mt++)
#pragma unroll
                for (int nt = 0; nt < 4; nt++) {
                    mma16816(acc[mt][nt], aH + mt * 4, bH + nt * 2);
                    mma16816(acc[mt][nt], aL + mt * 4, bH + nt * 2);
                    mma16816(acc[mt][nt], aH + mt * 4, bL + nt * 2);
                }
        }
        __syncthreads();   // protect buf^1 before next iteration's load

        // relation boundary: bias + PReLU -> run, reset acc
        if ((c & 3) == 3) {
            const int r = c >> 2;
#pragma unroll
            for (int nt = 0; nt < 4; nt++) {
                const float b0 = biasS[r * TN + wn + nt * 8 + t2];
                const float b1 = biasS[r * TN + wn + nt * 8 + t2 + 1];
#pragma unroll
                for (int mt = 0; mt < 2; mt++) {
                    float h;
                    h = acc[mt][nt][0] + b0; h = (h >= 0.f) ? h : alpha * h; run[mt][nt][0] += h;
                    h = acc[mt][nt][1] + b1; h = (h >= 0.f) ? h : alpha * h; run[mt][nt][1] += h;
                    h = acc[mt][nt][2] + b0; h = (h >= 0.f) ? h : alpha * h; run[mt][nt][2] += h;
                    h = acc[mt][nt][3] + b1; h = (h >= 0.f) ? h : alpha * h; run[mt][nt][3] += h;
                    acc[mt][nt][0] = 0.f; acc[mt][nt][1] = 0.f;
                    acc[mt][nt][2] = 0.f; acc[mt][nt][3] = 0.f;
                }
            }
        }
    }

    // mean over relations, store. c-frag rows: g / g+8; cols: t2, t2+1.
#pragma unroll
    for (int mt = 0; mt < 2; mt++) {
#pragma unroll
        for (int nt = 0; nt < 4; nt++) {
            const int row0 = bm0 + wm + mt * 16 + g;
            const int col  = bn0 + wn + nt * 8 + t2;
            float2 v0 = make_float2(run[mt][nt][0] * 0.25f, run[mt][nt][1] * 0.25f);
            float2 v1 = make_float2(run[mt][nt][2] * 0.25f, run[mt][nt][3] * 0.25f);
            *(float2*)(out + (size_t)row0 * OUT_FT + col)       = v0;
            *(float2*)(out + (size_t)(row0 + 8) * OUT_FT + col) = v1;
        }
    }
}

// ---------------------------------------------------------------------------
// Launch. Inputs (metadata order): features, neighbor_idx, W, b, prelu_a,
// node_list, k. node_list/k are unused by the reference math.
// ---------------------------------------------------------------------------
extern "C" void kernel_launch(void* const* d_in, const int* in_sizes, int n_in,
                              void* d_out, int out_size)
{
    const float* features = (const float*)d_in[0];
    const int*   nidx     = (const int*)d_in[1];
    const float* W        = (const float*)d_in[2];
    const float* bias     = (const float*)d_in[3];
    const float* prelu_a  = (const float*)d_in[4];
    float* out = (float*)d_out;

    // Idempotent attribute set (not a stream op; graph-capture safe).
    cudaFuncSetAttribute(rgcn_mma_kernel,
                         cudaFuncAttributeMaxDynamicSharedMemorySize, SMEM_DYN);

    // Fused gather (8192 blocks) + W prep (1024 blocks)
    prep_kernel<<<8192 + NB_REL * OUT_FT, 256>>>(features, nidx, W);

    dim3 grid(BATCH / TM, OUT_FT / TN);   // (64, 4) = 256 CTAs
    rgcn_mma_kernel<<<grid, 256, SMEM_DYN>>>(bias, prelu_a, out);
}